// round 3
// baseline (speedup 1.0000x reference)
#include <cuda_runtime.h>

// RoPE over x:(B=4, H=32, S=8192, D=64) fp32, token_position = arange(S).
//   Kernel 1: (cos,sin) table (S x 32) in a __device__ global (2 MB).
//             Manual double-precision range reduction (|r| <= pi) so sincosf
//             takes the fast polynomial path instead of Payne-Hanek.
//   Kernel 2: streaming rotate, 1 float4 (2 rotation pairs) per thread —
//             the round-1 form that hit 78.9% DRAM. Table reads are
//             L2-resident (128x reuse).

#define S_LEN   8192
#define HALF_D  32
#define LOG2_THETA 13.287712379549449     // log2(10000)
#define TWO_PI    6.283185307179586476925 // 2*pi in double
#define INV_2PI   0.159154943091895335769 // 1/(2*pi)

__device__ float2 g_rope_tbl[S_LEN * HALF_D];

__global__ void rope_build_table(const int* __restrict__ token_position, int total) {
    int t = blockIdx.x * blockDim.x + threadIdx.x;
    if (t >= total) return;
    int s = t >> 5;           // position index
    int j = t & 31;           // frequency index
    float pos = (float)token_position[s];
    // inv_freq in double, rounded to fp32 (matches fp32 theta**(-2j/d))
    float inv = (float)exp2(-(double)(2 * j) / 64.0 * LOG2_THETA);
    float ang = pos * inv;    // fp32 angle, same rounding as reference
    // Double-precision range reduction of the exact fp32 value:
    // |ang| <= 8191.x, k <= ~1304, error ~ k*ulp(2pi) ~ 4e-12 absolute.
    double a = (double)ang;
    double k = rint(a * INV_2PI);
    float r = (float)(a - k * TWO_PI);   // |r| <= pi -> sincosf fast path
    float sn, cn;
    sincosf(r, &sn, &cn);
    g_rope_tbl[t] = make_float2(cn, sn);
}

__global__ void __launch_bounds__(256)
rope_rotate(const float4* __restrict__ x, float4* __restrict__ out, int n4) {
    int i = blockIdx.x * blockDim.x + threadIdx.x;
    if (i >= n4) return;
    int within = i & 15;              // float4 index within the 64-elem row
    int s      = (i >> 4) & (S_LEN - 1);

    float4 v = x[i];
    const float4* tbl4 = reinterpret_cast<const float4*>(g_rope_tbl);
    float4 cs = __ldg(&tbl4[s * (HALF_D / 2) + within]);  // (c0,s0,c1,s1)

    float4 r;
    r.x = v.x * cs.x - v.y * cs.y;
    r.y = v.x * cs.y + v.y * cs.x;
    r.z = v.z * cs.z - v.w * cs.w;
    r.w = v.z * cs.w + v.w * cs.z;
    out[i] = r;
}

extern "C" void kernel_launch(void* const* d_in, const int* in_sizes, int n_in,
                              void* d_out, int out_size) {
    const float* x   = (const float*)d_in[0];
    const int*   tok = (const int*)d_in[1];
    int n  = in_sizes[0];      // 67,108,864 elements
    int P  = in_sizes[1];      // 8192 positions
    int n4 = n / 4;

    int tbl_total = P * HALF_D;
    rope_build_table<<<(tbl_total + 255) / 256, 256>>>(tok, tbl_total);
    rope_rotate<<<(n4 + 255) / 256, 256>>>((const float4*)x, (float4*)d_out, n4);
}

// round 4
// speedup vs baseline: 1.1396x; 1.1396x over previous
#include <cuda_runtime.h>

// RoPE over x:(B=4, H=32, S=8192, D=64) fp32, token_position = arange(S).
// SINGLE fused kernel: one block per sequence position.
//   - threads 0..31 compute the 32 (cos,sin) pairs for this position into
//     smem (double-precision range reduction -> fast sincosf path; matches
//     the fp32 JAX reference to ~2 ulp).
//   - all 256 threads then stream the B*H = 128 rows for this position:
//     2048 float4s per block, cs held in registers (loop-invariant).
// This removes the separate table kernel and its ~13us serialization gap.

#define S_LEN   8192
#define HALF_D  32
#define LOG2_THETA 13.287712379549449     // log2(10000)
#define TWO_PI    6.283185307179586476925
#define INV_2PI   0.159154943091895335769

__global__ void __launch_bounds__(256)
rope_fused(const float4* __restrict__ x, float4* __restrict__ out,
           const int* __restrict__ token_position, int nrows) // nrows = B*H
{
    __shared__ float2 cs_sh[HALF_D];

    int s   = blockIdx.x;
    int tid = threadIdx.x;

    if (tid < HALF_D) {
        float pos = (float)token_position[s];
        // inv_freq in double, rounded to fp32 (matches fp32 theta**(-2j/d))
        float inv = (float)exp2(-(double)(2 * tid) / 64.0 * LOG2_THETA);
        float ang = pos * inv;            // fp32 angle, reference rounding
        // double range reduction of the exact fp32 angle: |r| <= pi
        double a = (double)ang;
        double k = rint(a * INV_2PI);
        float  r = (float)(a - k * TWO_PI);
        float sn, cn;
        sincosf(r, &sn, &cn);             // fast polynomial path
        cs_sh[tid] = make_float2(cn, sn);
    }
    __syncthreads();

    int within = tid & 15;                // float4 index within 64-elem row
    int bh0    = tid >> 4;                // 0..15
    float4 cs  = reinterpret_cast<const float4*>(cs_sh)[within]; // (c0,s0,c1,s1)

    // 128 rows / 16 rows-per-iteration = 8 iterations
    #pragma unroll 4
    for (int bh = bh0; bh < nrows; bh += 16) {
        int i = (bh * S_LEN + s) * 16 + within;   // max ~16.7M < 2^31
        float4 v = x[i];
        float4 r;
        r.x = v.x * cs.x - v.y * cs.y;
        r.y = v.x * cs.y + v.y * cs.x;
        r.z = v.z * cs.z - v.w * cs.w;
        r.w = v.z * cs.w + v.w * cs.z;
        out[i] = r;
    }
}

extern "C" void kernel_launch(void* const* d_in, const int* in_sizes, int n_in,
                              void* d_out, int out_size) {
    const float* x   = (const float*)d_in[0];
    const int*   tok = (const int*)d_in[1];
    int n  = in_sizes[0];          // 67,108,864 elements
    int P  = in_sizes[1];          // 8192 positions (== S)
    int nrows = n / (P * 64);      // B*H = 128

    rope_fused<<<P, 256>>>((const float4*)x, (float4*)d_out, tok, nrows);
}

// round 5
// speedup vs baseline: 1.1486x; 1.0079x over previous
#include <cuda_runtime.h>

// RoPE over x:(B=4, H=32, S=8192, D=64) fp32, token_position = arange(S).
// Single fused kernel, one block per sequence position:
//   - threads 0..31 compute the 32 (cos,sin) pairs into smem (double range
//     reduction -> fast sincosf; matches fp32 JAX reference to ~2 ulp).
//   - all 256 threads stream the B*H = 128 rows for this position.
// This round: explicit MLP=4 — two batches of (4 independent LDG.128 ->
// 4 FMA+STG.128) per thread to raise DRAM sectors-in-flight.

#define S_LEN   8192
#define HALF_D  32
#define LOG2_THETA 13.287712379549449     // log2(10000)
#define TWO_PI    6.283185307179586476925
#define INV_2PI   0.159154943091895335769

__global__ void __launch_bounds__(256)
rope_fused(const float4* __restrict__ x, float4* __restrict__ out,
           const int* __restrict__ token_position, int nrows) // nrows = B*H = 128
{
    __shared__ float2 cs_sh[HALF_D];

    int s   = blockIdx.x;
    int tid = threadIdx.x;

    if (tid < HALF_D) {
        float pos = (float)token_position[s];
        float inv = (float)exp2(-(double)(2 * tid) / 64.0 * LOG2_THETA);
        float ang = pos * inv;            // fp32 angle, reference rounding
        double a = (double)ang;
        double k = rint(a * INV_2PI);
        float  r = (float)(a - k * TWO_PI);   // |r| <= pi
        float sn, cn;
        sincosf(r, &sn, &cn);
        cs_sh[tid] = make_float2(cn, sn);
    }
    __syncthreads();

    int within = tid & 15;                // float4 index within 64-elem row
    int bh0    = tid >> 4;                // 0..15
    float4 cs  = reinterpret_cast<const float4*>(cs_sh)[within];

    // 128 rows, 16 rows covered per "lane-group" -> 8 rows per thread,
    // processed as 2 batches of 4 with loads front-issued (MLP=4).
    int base = bh0 * (S_LEN * 16) + s * 16 + within;   // row bh0, this s
    const int rstride = 16 * S_LEN * 16;               // +16 rows in float4 units

    #pragma unroll
    for (int batch = 0; batch < 2; batch++) {
        int i0 = base + batch * (4 * rstride);
        float4 v0 = x[i0];
        float4 v1 = x[i0 + rstride];
        float4 v2 = x[i0 + 2 * rstride];
        float4 v3 = x[i0 + 3 * rstride];

        float4 r0, r1, r2, r3;
        r0.x = v0.x * cs.x - v0.y * cs.y;  r0.y = v0.x * cs.y + v0.y * cs.x;
        r0.z = v0.z * cs.z - v0.w * cs.w;  r0.w = v0.z * cs.w + v0.w * cs.z;
        r1.x = v1.x * cs.x - v1.y * cs.y;  r1.y = v1.x * cs.y + v1.y * cs.x;
        r1.z = v1.z * cs.z - v1.w * cs.w;  r1.w = v1.z * cs.w + v1.w * cs.z;
        r2.x = v2.x * cs.x - v2.y * cs.y;  r2.y = v2.x * cs.y + v2.y * cs.x;
        r2.z = v2.z * cs.z - v2.w * cs.w;  r2.w = v2.z * cs.w + v2.w * cs.z;
        r3.x = v3.x * cs.x - v3.y * cs.y;  r3.y = v3.x * cs.y + v3.y * cs.x;
        r3.z = v3.z * cs.z - v3.w * cs.w;  r3.w = v3.z * cs.w + v3.w * cs.z;

        out[i0]               = r0;
        out[i0 + rstride]     = r1;
        out[i0 + 2 * rstride] = r2;
        out[i0 + 3 * rstride] = r3;
    }
}

extern "C" void kernel_launch(void* const* d_in, const int* in_sizes, int n_in,
                              void* d_out, int out_size) {
    const float* x   = (const float*)d_in[0];
    const int*   tok = (const int*)d_in[1];
    int n  = in_sizes[0];          // 67,108,864 elements
    int P  = in_sizes[1];          // 8192 positions (== S)
    int nrows = n / (P * 64);      // B*H = 128

    rope_fused<<<P, 256>>>((const float4*)x, (float4*)d_out, tok, nrows);
}